// round 17
// baseline (speedup 1.0000x reference)
#include <cuda_runtime.h>
#include <cuda_fp16.h>
#include <cstdint>

// ---------------- SMEM layout (bytes) ----------------
#define SM_BIAS   0                    // 256 floats
#define SM_BPROJ  1024                 // 16 floats
#define SM_W      1152                 // W image: 256 rows x 592B = 151552
#define W_STRIDE  592                  // 296 halves (288 used + pad), conflict-free ldmatrix
#define SM_WP     (1152 + 151552)      // 152704: W_proj 16 rows x 528B = 8448
#define WP_STRIDE 528
#define SM_A      (152704 + 8448)      // 161152: A fp16 staging, 3 groups x 18944
#define A_GRP     18944                // 32 rows x 592B (h cols 0..255, x 256..279, zero 280..295)
#define A_STRIDE  592
#define SM_TOTAL  (161152 + 3 * 18944) // 217984

#define W_U4   9472                    // 151552 / 16
#define WP_U4  528                     // 8448 / 16

// Pre-converted fp16 weight images (static device scratch — no allocation)
__device__ uint4 g_w[W_U4];            // [n 0..255][k 0..295 halves]; k<256=W_hh, 256..279=W_ih, pad 0
__device__ uint4 g_wp[WP_U4];          // [n 0..15][k 0..263 halves]; n<12,k<256=W_proj else 0

static __device__ __forceinline__ uint32_t smem_u32(const void* p) {
    uint32_t r;
    asm("{ .reg .u64 t; cvta.to.shared.u64 t, %1; cvt.u32.u64 %0, t; }" : "=r"(r) : "l"(p));
    return r;
}
static __device__ __forceinline__ uint32_t pack2(float a, float b) {
    __half2 h = __floats2half2_rn(a, b);
    return *reinterpret_cast<uint32_t*>(&h);
}
static __device__ __forceinline__ float2 unpack2(uint32_t v) {
    __half2 h = *reinterpret_cast<__half2*>(&v);
    return __half22float2(h);
}
static __device__ __forceinline__ void cp16(uint32_t dst, const void* src) {
    asm volatile("cp.async.cg.shared.global [%0], [%1], 16;" :: "r"(dst), "l"(src));
}
#define CP_COMMIT()  asm volatile("cp.async.commit_group;" ::: "memory")
#define CP_WAIT(n)   asm volatile("cp.async.wait_group %0;" :: "n"(n) : "memory")

static __device__ __forceinline__ void lds32(uint32_t& v, uint32_t a) {
    asm volatile("ld.shared.b32 %0, [%1];" : "=r"(v) : "r"(a));
}
static __device__ __forceinline__ void lds64(uint32_t& v0, uint32_t& v1, uint32_t a) {
    asm volatile("ld.shared.v2.b32 {%0,%1}, [%2];" : "=r"(v0), "=r"(v1) : "r"(a));
}
static __device__ __forceinline__ void ldsf2(float& v0, float& v1, uint32_t a) {
    asm volatile("ld.shared.v2.f32 {%0,%1}, [%2];" : "=f"(v0), "=f"(v1) : "r"(a));
}
static __device__ __forceinline__ void stsf2(uint32_t a, float v0, float v1) {
    asm volatile("st.shared.v2.f32 [%0], {%1,%2};" :: "r"(a), "f"(v0), "f"(v1));
}
static __device__ __forceinline__ void sts32(uint32_t a, uint32_t v) {
    asm volatile("st.shared.b32 [%0], %1;" :: "r"(a), "r"(v));
}
static __device__ __forceinline__ void sts64(uint32_t a, uint32_t v0, uint32_t v1) {
    asm volatile("st.shared.v2.b32 [%0], {%1,%2};" :: "r"(a), "r"(v0), "r"(v1));
}
static __device__ __forceinline__ void ldmatrix4(uint32_t& a0, uint32_t& a1,
                                                 uint32_t& a2, uint32_t& a3, uint32_t addr) {
    asm volatile("ldmatrix.sync.aligned.m8n8.x4.shared.b16 {%0,%1,%2,%3}, [%4];"
                 : "=r"(a0), "=r"(a1), "=r"(a2), "=r"(a3) : "r"(addr));
}
#define MMA16816(c0, c1, c2, c3, a0, a1, a2, a3, b0, b1)                          \
    asm volatile("mma.sync.aligned.m16n8k16.row.col.f32.f16.f16.f32 "             \
                 "{%0,%1,%2,%3},{%4,%5,%6,%7},{%8,%9},{%0,%1,%2,%3};"             \
                 : "+f"(c0), "+f"(c1), "+f"(c2), "+f"(c3)                          \
                 : "r"(a0), "r"(a1), "r"(a2), "r"(a3), "r"(b0), "r"(b1))
#define BAR_GRP(id) asm volatile("bar.sync %0, 128;" :: "r"(id) : "memory")

static __device__ __forceinline__ uint32_t tanh16x2(uint32_t z) {
    uint32_t r;
    asm("tanh.approx.f16x2 %0, %1;" : "=r"(r) : "r"(z));
    return r;
}

// ================= prep: fp32 -> fp16 padded weight images =================
__global__ void prep_kernel(const float* __restrict__ W_ih, const float* __restrict__ W_hh,
                            const float* __restrict__ W_proj) {
    int idx = blockIdx.x * 256 + threadIdx.x;
    if (idx < 256 * 296) {
        int n = idx / 296, k = idx % 296;
        float v = 0.0f;
        if (k < 256)      v = W_hh[n * 256 + k];
        else if (k < 280) v = W_ih[n * 24 + (k - 256)];
        reinterpret_cast<__half*>(g_w)[idx] = __float2half_rn(v);
    } else if (idx < 256 * 296 + 16 * 264) {
        int r = idx - 256 * 296;          // 0 .. 4223
        int n = r / 264, k = r % 264;
        float v = (n < 12 && k < 256) ? W_proj[n * 256 + k] : 0.0f;
        reinterpret_cast<__half*>(g_wp)[r] = __float2half_rn(v);
    }
}

// ====== persistent fused kernel: 384 thr; 3 groups x 4 warps; SMEM-staged h stores ======
__global__ void __launch_bounds__(384, 1)
rnn_kernel(const float* __restrict__ xin, const float* __restrict__ hidden,
           const float* __restrict__ b_ih, const float* __restrict__ b_hh,
           const float* __restrict__ b_proj,
           float* __restrict__ out, float* __restrict__ h_out, int ntiles) {
    extern __shared__ char smem[];
    const uint32_t sb = smem_u32(smem);
    float* sbias  = reinterpret_cast<float*>(smem + SM_BIAS);
    float* sbproj = reinterpret_cast<float*>(smem + SM_BPROJ);

    const int tid  = threadIdx.x;
    const int w    = tid >> 5;
    const int lane = tid & 31;
    const int g    = lane >> 2;          // fragment row group 0..7
    const int c0   = (lane & 3) * 2;     // fragment col base 0,2,4,6
    const int tg   = lane & 3;
    const int grp  = w >> 2;             // 0..2
    const int nq   = w & 3;              // N-quarter: cols [nq*64, nq*64+64)
    const int pt   = (nq << 5) | lane;   // 0..127 within group

    // ---- resident W load (once per CTA) ----
#pragma unroll
    for (int it = 0; it < 25; it++) {
        int i = tid + it * 384;
        if (i < W_U4) cp16(sb + SM_W + i * 16, g_w + i);
    }
#pragma unroll
    for (int it = 0; it < 2; it++) {
        int i = tid + it * 384;
        if (i < WP_U4) cp16(sb + SM_WP + i * 16, g_wp + i);
    }
    CP_COMMIT();
    if (tid < 256) sbias[tid] = b_ih[tid] + b_hh[tid];
    if (tid < 16) sbproj[tid] = (tid < 12) ? b_proj[tid] : 0.0f;
    CP_WAIT(0);
    __syncthreads();

    // ---- ldmatrix B base (matrix m = lane>>3: nt-parity m>>1, k-half m&1) ----
    const int mrole = lane >> 3, mrow = lane & 7;
    const uint32_t wq0 = sb + SM_W +
        (uint32_t)((nq * 64 + (mrole >> 1) * 8 + mrow) * W_STRIDE) + (mrole & 1) * 16;
    // proj B bases: this quarter's K-chunk, n-tiles 0 and 1
    const uint32_t pbase = sb + SM_WP + (uint32_t)(nq * 128) + tg * 4;
    const uint32_t pb0 = pbase + (uint32_t)(g * WP_STRIDE);
    const uint32_t pb1 = pbase + (uint32_t)((8 + g) * WP_STRIDE);
    // this group's A staging buffer; h image + proj scratch alias it (time-disjoint)
    const uint32_t ab   = sb + SM_A + (uint32_t)grp * A_GRP;
    const uint32_t am0  = ab + (uint32_t)(lane & 15) * A_STRIDE + (lane >> 4) * 16;
    const uint32_t am1  = am0 + 16 * A_STRIDE;
    const uint32_t scrW = ab + (uint32_t)nq * 2304;
    // per-thread pad-zero slot (A layout bytes 560..575 of each row)
    const uint32_t padz = ab + (uint32_t)(pt >> 2) * A_STRIDE + 560 + (pt & 3) * 4;
    const int barid = grp + 1;

    const int ngrp = gridDim.x * 3;
    int t = blockIdx.x * 3 + grp;

    // ---- prologue: stage first tile ----
    {
        const float4* hsrc = (const float4*)(hidden + (size_t)t * 32 * 256);
#pragma unroll
        for (int j = 0; j < 16; j++) {
            const int f4 = j * 128 + pt;
            float4 v = hsrc[f4];
            sts64(ab + (uint32_t)(f4 >> 6) * A_STRIDE + (f4 & 63) * 8,
                  pack2(v.x, v.y), pack2(v.z, v.w));
        }
        const float2* xsrc = (const float2*)(xin + (size_t)t * 32 * 24);
#pragma unroll
        for (int j = 0; j < 3; j++) {
            const int j2 = j * 128 + pt;
            const int row = j2 / 12, cc = j2 % 12;
            float2 f = xsrc[j2];
            sts32(ab + (uint32_t)row * A_STRIDE + 512 + cc * 4, pack2(f.x, f.y));
        }
        sts32(padz, 0u);
    }

    for (; t < ntiles; t += ngrp) {
        const size_t r0 = (size_t)t * 32;

        // ---- acc init = bias ----
        float acc[64];
#pragma unroll
        for (int q = 0; q < 4; q++)
#pragma unroll
            for (int nt = 0; nt < 2; nt++) {
                float2 bb = *(const float2*)(sbias + nq * 64 + q * 16 + nt * 8 + c0);
                const int i = q * 16 + nt * 8;
                acc[i + 0] = bb.x; acc[i + 1] = bb.y; acc[i + 2] = bb.x; acc[i + 3] = bb.y;
                acc[i + 4] = bb.x; acc[i + 5] = bb.y; acc[i + 6] = bb.x; acc[i + 7] = bb.y;
            }

        BAR_GRP(barid);   // B0: staged A (and pad zeros) visible to whole group

        // ---- MMA1: uniform 18 k-steps ----
#pragma unroll
        for (int ks = 0; ks < 18; ks++) {
            uint32_t a0, a1, a2, a3, a4, a5, a6, a7;
            ldmatrix4(a0, a1, a2, a3, am0 + ks * 32);
            ldmatrix4(a4, a5, a6, a7, am1 + ks * 32);
#pragma unroll
            for (int q = 0; q < 4; q++) {
                uint32_t b0, b1, b2, b3;
                ldmatrix4(b0, b1, b2, b3,
                          wq0 + (uint32_t)q * (16 * W_STRIDE) + ks * 32);
                const int i = q * 16;
                MMA16816(acc[i + 0], acc[i + 1], acc[i + 2], acc[i + 3],
                         a0, a1, a2, a3, b0, b1);
                MMA16816(acc[i + 4], acc[i + 5], acc[i + 6], acc[i + 7],
                         a4, a5, a6, a7, b0, b1);
                MMA16816(acc[i + 8], acc[i + 9], acc[i + 10], acc[i + 11],
                         a0, a1, a2, a3, b2, b3);
                MMA16816(acc[i + 12], acc[i + 13], acc[i + 14], acc[i + 15],
                         a4, a5, a6, a7, b2, b3);
            }
        }

        // ---- tanh in f16x2; hh feeds proj + h image directly ----
        uint32_t hh[32];
#pragma unroll
        for (int j = 0; j < 32; j++)
            hh[j] = tanh16x2(pack2(acc[2 * j], acc[2 * j + 1]));

        // ---- proj partials: A frags straight from hh ----
        float pa[16];
#pragma unroll
        for (int i = 0; i < 16; i++) pa[i] = 0.0f;
#pragma unroll
        for (int pk = 0; pk < 4; pk++) {
            const int j = pk * 8;
            uint32_t b00, b01, b10, b11;
            lds32(b00, pb0 + pk * 32); lds32(b01, pb0 + pk * 32 + 16);
            lds32(b10, pb1 + pk * 32); lds32(b11, pb1 + pk * 32 + 16);
            MMA16816(pa[0],  pa[1],  pa[2],  pa[3],
                     hh[j + 0], hh[j + 1], hh[j + 4], hh[j + 5], b00, b01);
            MMA16816(pa[4],  pa[5],  pa[6],  pa[7],
                     hh[j + 2], hh[j + 3], hh[j + 6], hh[j + 7], b00, b01);
            MMA16816(pa[8],  pa[9],  pa[10], pa[11],
                     hh[j + 0], hh[j + 1], hh[j + 4], hh[j + 5], b10, b11);
            MMA16816(pa[12], pa[13], pa[14], pa[15],
                     hh[j + 2], hh[j + 3], hh[j + 6], hh[j + 7], b10, b11);
        }

        // ---- prefetch next tile's A/x into registers ----
        const int tn = t + ngrp;
        const bool pf = tn < ntiles;
        uint32_t pv2[32];
        float2 px[3];
        if (pf) {
            const float4* hsrc = (const float4*)(hidden + (size_t)tn * 32 * 256);
            {
                float4 tmp[8];
#pragma unroll
                for (int j = 0; j < 8; j++) tmp[j] = hsrc[j * 128 + pt];
#pragma unroll
                for (int j = 0; j < 8; j++) {
                    pv2[2 * j]     = pack2(tmp[j].x, tmp[j].y);
                    pv2[2 * j + 1] = pack2(tmp[j].z, tmp[j].w);
                }
            }
            {
                float4 tmp[8];
#pragma unroll
                for (int j = 0; j < 8; j++) tmp[j] = hsrc[(j + 8) * 128 + pt];
#pragma unroll
                for (int j = 0; j < 8; j++) {
                    pv2[16 + 2 * j] = pack2(tmp[j].x, tmp[j].y);
                    pv2[17 + 2 * j] = pack2(tmp[j].z, tmp[j].w);
                }
            }
            const float2* xsrc = (const float2*)(xin + (size_t)tn * 32 * 24);
#pragma unroll
            for (int j = 0; j < 3; j++) px[j] = xsrc[j * 128 + pt];
        }

        BAR_GRP(barid);   // B1: whole group done reading A (region reused for h image)

        // ---- STS h image: flat 32 rows x 512B fp16, 16B-unit XOR swizzle ----
        // physical unit = nq*8 + ((2q+nt) ^ (row&7)); quarter base = nq*128 BYTES (FIX)
#pragma unroll
        for (int q = 0; q < 4; q++)
#pragma unroll
            for (int nt = 0; nt < 2; nt++)
#pragma unroll
                for (int rr = 0; rr < 4; rr++) {
                    const int j = q * 8 + nt * 4 + rr;
                    const uint32_t row = (uint32_t)(g + 8 * rr);
                    const uint32_t u = (uint32_t)(2 * q + nt);
                    sts32(ab + row * 512 + (uint32_t)(nq * 128) +
                              ((u ^ (row & 7)) << 4) + (uint32_t)(tg * 4),
                          hh[j]);
                }
        BAR_GRP(barid);   // Bh: h image visible

        // ---- cooperative copy h image -> h_out (coalesced STG.128) ----
        {
            float* hbase = h_out + r0 * 256;
#pragma unroll
            for (int k = 0; k < 16; k++) {
                const uint32_t K = (uint32_t)(nq * 16 + k);
                const uint32_t unit = K * 16 + (uint32_t)(lane >> 1);
                const uint32_t row = unit >> 5;
                const uint32_t u = unit & 31;
                uint32_t d0, d1;
                lds64(d0, d1, ab + row * 512 + ((u ^ (row & 7)) << 4) + (uint32_t)((lane & 1) * 8));
                float2 f0 = unpack2(d0), f1 = unpack2(d1);
                *(float4*)(hbase + K * 128 + lane * 4) = make_float4(f0.x, f0.y, f1.x, f1.y);
            }
        }
        BAR_GRP(barid);   // Bh2: h image reads done (scratch reuses that memory)

        // ---- write 32x16 partials to this warp's scratch region ----
#pragma unroll
        for (int nt = 0; nt < 2; nt++)
#pragma unroll
            for (int half = 0; half < 2; half++) {
                const int i = nt * 8 + half * 4;
                const uint32_t base = scrW + (uint32_t)((g + half * 16) * 72 + (nt * 8 + c0) * 4);
                stsf2(base,          pa[i + 0], pa[i + 1]);
                stsf2(base + 8 * 72, pa[i + 2], pa[i + 3]);
            }
        BAR_GRP(barid);   // B2: partials visible

        // ---- sum 4 partials; warp nq handles tile rows nq*8+g; quad = 1 row ----
        float l[4];
        l[0] = sbproj[c0]; l[1] = sbproj[c0 + 1];
        l[2] = sbproj[8 + c0]; l[3] = sbproj[9 + c0];
        {
            const uint32_t rbase = ab + (uint32_t)((nq * 8 + g) * 72);
#pragma unroll
            for (int j = 0; j < 4; j++) {
                float p0, p1;
                ldsf2(p0, p1, rbase + j * 2304 + c0 * 4);
                l[0] += p0; l[1] += p1;
                ldsf2(p0, p1, rbase + j * 2304 + (8 + c0) * 4);
                l[2] += p0; l[3] += p1;
            }
        }

        {
            const bool v1 = (8 + c0) < 12;
            if (!v1) { l[2] = l[3] = -1e30f; }

            float mx = fmaxf(fmaxf(l[0], l[1]), fmaxf(l[2], l[3]));
            mx = fmaxf(mx, __shfl_xor_sync(0xFFFFFFFFu, mx, 1));
            mx = fmaxf(mx, __shfl_xor_sync(0xFFFFFFFFu, mx, 2));

            float s = 0.f;
#pragma unroll
            for (int j = 0; j < 4; j++) { l[j] = __expf(l[j] - mx); s += l[j]; }
            s += __shfl_xor_sync(0xFFFFFFFFu, s, 1);
            s += __shfl_xor_sync(0xFFFFFFFFu, s, 2);
            const float inv = __fdividef(1.0f, s);

            float* o = out + (r0 + nq * 8 + g) * 12;
            *(float2*)(o + c0) = make_float2(l[0] * inv, l[1] * inv);
            if (v1) *(float2*)(o + 8 + c0) = make_float2(l[2] * inv, l[3] * inv);
        }

        BAR_GRP(barid);   // B3: scratch reads done before next tile's A staging

        // ---- store prefetched next-tile A/x + re-zero pads ----
        if (pf) {
#pragma unroll
            for (int j = 0; j < 16; j++) {
                const int f4 = j * 128 + pt;
                sts64(ab + (uint32_t)(f4 >> 6) * A_STRIDE + (f4 & 63) * 8,
                      pv2[2 * j], pv2[2 * j + 1]);
            }
#pragma unroll
            for (int j = 0; j < 3; j++) {
                const int j2 = j * 128 + pt;
                const int row = j2 / 12, cc = j2 % 12;
                sts32(ab + (uint32_t)row * A_STRIDE + 512 + cc * 4, pack2(px[j].x, px[j].y));
            }
            sts32(padz, 0u);
        }
    }
}

extern "C" void kernel_launch(void* const* d_in, const int* in_sizes, int n_in,
                              void* d_out, int out_size) {
    const float* x      = (const float*)d_in[0];
    const float* hidden = (const float*)d_in[1];
    const float* W_ih   = (const float*)d_in[2];
    const float* b_ih   = (const float*)d_in[3];
    const float* W_hh   = (const float*)d_in[4];
    const float* b_hh   = (const float*)d_in[5];
    const float* W_proj = (const float*)d_in[6];
    const float* b_proj = (const float*)d_in[7];

    const int N = in_sizes[0] / 24;            // 524288
    float* out   = (float*)d_out;              // [N,12] softmax
    float* h_out = out + (size_t)N * 12;       // [N,256] h_new

    cudaFuncSetAttribute(rnn_kernel, cudaFuncAttributeMaxDynamicSharedMemorySize, SM_TOTAL);

    prep_kernel<<<313, 256>>>(W_ih, W_hh, W_proj);               // guarded
    rnn_kernel<<<152, 384, SM_TOTAL>>>(x, hidden, b_ih, b_hh, b_proj,
                                       out, h_out, N / 32);      // persistent; tiles of 32 rows
}